// round 9
// baseline (speedup 1.0000x reference)
#include <cuda_runtime.h>

#define NB 32
#define NQ 1024
#define NG 64
#define NT 128
#define MAXD 16
#define BIG 1e300

// 8 MB scratch: transposed cost cost[b][i][j], i = gt row, j = proposal col
__device__ float g_cost[NB * NG * NQ];

// ---------------------------------------------------------------------------
// Cost build (exact IEEE order, no FMA contraction -> bit-matches reference fp32)
// ---------------------------------------------------------------------------
__global__ void build_cost_kernel(const float* __restrict__ obj,
                                  const float* __restrict__ cd,
                                  const float* __restrict__ gi) {
    int t = blockIdx.x * blockDim.x + threadIdx.x;
    if (t >= NB * NG * NQ) return;
    int j = t & (NQ - 1);
    int i = (t >> 10) & (NG - 1);
    int b = t >> 16;
    float o = obj[b * NQ + j];
    int src = (b * NQ + j) * NG + i;
    float a0 = __fmul_rn(5.0f, -o);
    float a1 = __fmul_rn(10.0f, cd[src]);
    float a2 = __fmul_rn(2.0f, -gi[src]);
    g_cost[t] = __fadd_rn(__fadd_rn(a0, a1), a2);
}

// order-preserving u32 key for a float
__device__ __forceinline__ unsigned int flip32(unsigned int b) {
    return (b & 0x80000000u) ? ~b : (b | 0x80000000u);
}
__device__ __forceinline__ float unflip32(unsigned int k) {
    unsigned int b = (k & 0x80000000u) ? (k & 0x7fffffffu) : ~k;
    return __uint_as_float(b);
}
// order-preserving u64 key for a double, index in low 10 bits
__device__ __forceinline__ unsigned long long packkey(double x, int idx) {
    long long sb = __double_as_longlong(x);
    unsigned long long ub = (unsigned long long)sb;
    ub = (sb < 0) ? ~ub : (ub | 0x8000000000000000ULL);
    return (ub & ~1023ULL) | (unsigned long long)idx;
}

// ---------------------------------------------------------------------------
// per-row argmin over columns (first-min tie-break), optionally skipping
// columns with v != 0 ("dirty"). 2 threads per row, 512 cols each.
// ---------------------------------------------------------------------------
__device__ void precompute_top1(const float* __restrict__ cost,
                                const double* s_v,
                                unsigned long long* s_top1,
                                int start, int g, bool skip_dirty, int tid) {
    for (int r = start + tid; r < g; r += NT) s_top1[r] = ~0ULL;
    __syncthreads();
    int row = start + (tid >> 1);
    if (row < g) {
        int half = tid & 1;
        unsigned long long best = ~0ULL;
        const float* crow = cost + row * NQ + half * 512;
        for (int c = 0; c < 512; c += 4) {
            float4 f = *(const float4*)(crow + c);
            int j0 = half * 512 + c;
#define PPK(ff, jj)                                                              \
            if (!skip_dirty || s_v[jj] == 0.0) {                                 \
                unsigned long long kk =                                          \
                    ((unsigned long long)flip32(__float_as_uint(ff)) << 10)      \
                    | (unsigned)(jj);                                            \
                if (kk < best) best = kk;                                        \
            }
            PPK(f.x, j0) PPK(f.y, j0 + 1) PPK(f.z, j0 + 2) PPK(f.w, j0 + 3)
#undef PPK
        }
        atomicMin(&s_top1[row], best);
    }
    __syncthreads();
}

// ---------------------------------------------------------------------------
// Full JV shortest-augmenting-path Dijkstra for one row (rare path).
// Exact reference rounding: r = ((mv + c) - u[i]) - v[j].
// ---------------------------------------------------------------------------
__device__ void run_dijkstra(int cur, int g, const float* __restrict__ cost,
                             double* s_v, double* s_short, double* s_u,
                             short* s_row4col, short* s_col4row,
                             unsigned char* s_path, unsigned char* s_SC,
                             unsigned char* s_inSR,
                             short* s_dirty, int* s_ndirty,
                             unsigned long long* s_packed,
                             int* s_i, int* s_sink, double* s_minval,
                             int tid) {
    for (int j = tid; j < NQ; j += NT) { s_short[j] = BIG; s_SC[j] = 0; }
    for (int i = tid; i < g; i += NT) s_inSR[i] = (i == cur) ? 1 : 0;
    if (tid == 0) { *s_i = cur; *s_sink = -1; *s_minval = 0.0; *s_packed = ~0ULL; }
    __syncthreads();

    while (true) {
        const int i = *s_i;
        const double mv = *s_minval;
        const double ui = s_u[i];
        const float* __restrict__ crow = cost + i * NQ;
        unsigned long long best = ~0ULL;
#pragma unroll
        for (int k = 0; k < 8; ++k) {
            const int j = tid + (k << 7);
            if (!s_SC[j]) {
                double r = ((mv + (double)__ldg(crow + j)) - ui) - s_v[j];
                double sh = s_short[j];
                if (r < sh) { sh = r; s_short[j] = r; s_path[j] = (unsigned char)i; }
                unsigned long long kk = packkey(sh, j);
                if (kk < best) best = kk;
            }
        }
        atomicMin(s_packed, best);
        __syncthreads();
        if (tid == 0) {
            const int bidx = (int)(*s_packed & 1023ULL);
            *s_minval = s_short[bidx];
            *s_packed = ~0ULL;
            s_SC[bidx] = 1;
            const int rc = s_row4col[bidx];
            if (rc < 0) *s_sink = bidx;
            else { *s_i = rc; s_inSR[rc] = 1; }
        }
        __syncthreads();
        if (*s_sink >= 0) break;
    }

    const double mv = *s_minval;
    const int sink = *s_sink;
    // dual updates (pre-augment col4row)
    for (int i = tid; i < g; i += NT) {
        if (i == cur) s_u[i] += mv;
        else if (s_inSR[i]) s_u[i] += mv - s_short[s_col4row[i]];
    }
    for (int j = tid; j < NQ; j += NT) {
        if (s_SC[j]) {
            double d = mv - s_short[j];
            double old = s_v[j];
            s_v[j] = old - d;
            if (old == 0.0 && s_v[j] != 0.0) {
                int p = atomicAdd(s_ndirty, 1);
                if (p < MAXD) s_dirty[p] = (short)j;
            }
        }
    }
    __syncthreads();
    if (tid == 0) {
        int j = sink;
        while (true) {
            const int i = s_path[j];
            s_row4col[j] = (short)i;
            const short nj = s_col4row[i];
            s_col4row[i] = (short)j;
            j = nj;
            if (i == cur) break;
        }
    }
    __syncthreads();
}

// ---------------------------------------------------------------------------
// Solver: greedy first-pop fast path + exact Dijkstra fallback. 1 CTA/batch.
// ---------------------------------------------------------------------------
__global__ void __launch_bounds__(NT, 1)
solve_kernel(const int* __restrict__ ngt, float* __restrict__ out) {
    const int b = blockIdx.x;
    const int tid = threadIdx.x;

    __shared__ double s_v[NQ];
    __shared__ double s_short[NQ];
    __shared__ short s_row4col[NQ];
    __shared__ unsigned char s_path[NQ];
    __shared__ unsigned char s_SC[NQ];
    __shared__ double s_u[NG];
    __shared__ short s_col4row[NG];
    __shared__ unsigned char s_inSR[NG];
    __shared__ unsigned long long s_top1[NG];
    __shared__ float s_dirty_c[NG][MAXD];
    __shared__ short s_dirty[MAXD];
    __shared__ int s_ndirty, s_force, s_h;
    __shared__ unsigned long long s_packed;
    __shared__ int s_i, s_sink;
    __shared__ double s_minval;

    float* outi = out + b * NQ;              // per_prop_gt_inds (as float)
    float* outm = out + NB * NQ + b * NQ;    // proposal_matched_mask
    for (int j = tid; j < NQ; j += NT) { outi[j] = 0.0f; outm[j] = 0.0f; }

    const int g = ngt[b];
    if (g <= 0) return;

    const float* __restrict__ cost = g_cost + b * NG * NQ;

    for (int j = tid; j < NQ; j += NT) { s_v[j] = 0.0; s_row4col[j] = -1; }
    for (int i = tid; i < g; i += NT) { s_u[i] = 0.0; s_col4row[i] = -1; }
    if (tid == 0) { s_ndirty = 0; s_force = 0; }
    __syncthreads();

    precompute_top1(cost, s_v, s_top1, 0, g, false, tid);

    int seg = 0;
    while (seg < g) {
        // tid0 sweeps rows greedily with zero barriers until a heavy event
        if (tid == 0) {
            int cur = seg;
            int h = g;
            const int nd = s_ndirty;
            const int forceh = s_force;
            while (cur < g) {
                if (forceh) { h = cur; break; }
                // clean candidate (exact: r = (double)c when u=v=0)
                const unsigned long long k = s_top1[cur];
                int bj = (int)(k & 1023ULL);
                double bv = (double)unflip32((unsigned int)(k >> 10));
                // dirty candidates: exact r = ((0+c)-0) - v[j]
                for (int d = 0; d < nd; ++d) {
                    const int jd = s_dirty[d];
                    const double r = (double)s_dirty_c[cur][d] - s_v[jd];
                    if (r < bv || (r == bv && jd < bj)) { bv = r; bj = jd; }
                }
                if (s_row4col[bj] >= 0) { h = cur; break; }   // collision -> heavy
                s_row4col[bj] = (short)cur;
                s_col4row[cur] = (short)bj;
                s_u[cur] = bv;                                // u[cur] += min_val
                ++cur;
            }
            s_h = h;
        }
        __syncthreads();
        const int h = s_h;
        if (h >= g) break;

        const int nd0 = s_ndirty;
        run_dijkstra(h, g, cost, s_v, s_short, s_u, s_row4col, s_col4row,
                     s_path, s_SC, s_inSR, s_dirty, &s_ndirty,
                     &s_packed, &s_i, &s_sink, &s_minval, tid);

        if (tid == 0 && s_ndirty > MAXD) s_force = 1;
        __syncthreads();
        if (!s_force && s_ndirty != nd0) {
            // new dirty columns: rebuild clean top1 for remaining rows,
            // and cache dirty-column costs for the serial loop
            precompute_top1(cost, s_v, s_top1, h + 1, g, true, tid);
            const int nd = s_ndirty;
            const int nrows = g - (h + 1);
            for (int x = tid; x < nrows * nd; x += NT) {
                const int r = h + 1 + x / nd;
                const int d = x - (x / nd) * nd;
                s_dirty_c[r][d] = __ldg(cost + r * NQ + s_dirty[d]);
            }
            __syncthreads();
        }
        seg = h + 1;
    }

    // outputs: proposal p = col4row[i] gets index i, mask 1
    for (int i = tid; i < g; i += NT) {
        const int p = s_col4row[i];
        outi[p] = (float)i;
        outm[p] = 1.0f;
    }
}

extern "C" void kernel_launch(void* const* d_in, const int* in_sizes, int n_in,
                              void* d_out, int out_size) {
    const float* obj = (const float*)d_in[1];
    const float* cd  = (const float*)d_in[2];
    const float* gi  = (const float*)d_in[3];
    const int* ngt   = (const int*)d_in[4];
    float* out = (float*)d_out;

    const int total = NB * NG * NQ;
    build_cost_kernel<<<(total + 255) / 256, 256>>>(obj, cd, gi);
    solve_kernel<<<NB, NT>>>(ngt, out);
}

// round 11
// speedup vs baseline: 2.1545x; 2.1545x over previous
#include <cuda_runtime.h>

#define NB 32
#define NQ 1024
#define NG 64
#define NT 128           // threads per solver CTA
#define KPT 8            // columns per thread
#define BIG 1e300
#define MARGIN 1e-3f

// 8 MB scratch: transposed cost cost[b][i][j], i = gt row, j = proposal col
__device__ float g_cost[NB * NG * NQ];

// ---------------------------------------------------------------------------
// Cost build (exact IEEE order, no FMA contraction -> bit-matches reference fp32)
// ---------------------------------------------------------------------------
__global__ void build_cost_kernel(const float* __restrict__ obj,
                                  const float* __restrict__ cd,
                                  const float* __restrict__ gi) {
    int t = blockIdx.x * blockDim.x + threadIdx.x;
    if (t >= NB * NG * NQ) return;
    int j = t & (NQ - 1);
    int i = (t >> 10) & (NG - 1);
    int b = t >> 16;
    float o = obj[b * NQ + j];
    int src = (b * NQ + j) * NG + i;
    float a0 = __fmul_rn(5.0f, -o);
    float a1 = __fmul_rn(10.0f, cd[src]);
    float a2 = __fmul_rn(2.0f, -gi[src]);
    g_cost[t] = __fadd_rn(__fadd_rn(a0, a1), a2);
}

// Order-preserving uint64 key for a double, column index in low 10 bits
// (near-equal values tie toward the smaller index == numpy first-min rule).
__device__ __forceinline__ unsigned long long packkey(double x, int idx) {
    long long sb = __double_as_longlong(x);
    unsigned long long ub = (unsigned long long)sb;
    ub = (sb < 0) ? ~ub : (ub | 0x8000000000000000ULL);
    return (ub & ~1023ULL) | (unsigned long long)idx;
}

// ---------------------------------------------------------------------------
// Jonker-Volgenant shortest-augmenting-path LSA, one CTA per batch (R2 base).
// Relax loop: branchless fp32 screen -> ONE divergent exact-fp64 region.
// ---------------------------------------------------------------------------
__global__ void __launch_bounds__(NT, 1)
solve_kernel(const int* __restrict__ ngt, float* __restrict__ out) {
    const int b = blockIdx.x;
    const int tid = threadIdx.x;

    __shared__ double s_short[NQ];          // exact fp64 shortest (write-through)
    __shared__ short s_row4col[NQ];
    __shared__ unsigned char s_path[NQ];
    __shared__ double s_u[NG];
    __shared__ short s_col4row[NG];
    __shared__ unsigned char s_inSR[NG];
    __shared__ int s_i, s_sink, s_bidx;
    __shared__ double s_minval;
    __shared__ unsigned long long s_packed;

    float* outi = out + b * NQ;             // per_prop_gt_inds (as float)
    float* outm = out + NB * NQ + b * NQ;   // proposal_matched_mask

    for (int j = tid; j < NQ; j += NT) { outi[j] = 0.0f; outm[j] = 0.0f; }

    const int g = ngt[b];
    if (g <= 0) return;

    const float* __restrict__ cost = g_cost + b * NG * NQ;

    double v_reg[KPT], sh_reg[KPT];
    float  vf[KPT], shf[KPT];
#pragma unroll
    for (int k = 0; k < KPT; ++k) { v_reg[k] = 0.0; vf[k] = 0.0f; }

    for (int j = tid; j < NQ; j += NT) s_row4col[j] = -1;
    for (int i = tid; i < g; i += NT) { s_u[i] = 0.0; s_col4row[i] = -1; }
    __syncthreads();

    for (int cur = 0; cur < g; ++cur) {
        unsigned scmask = 0;
        double lbest = BIG;
        int lidx = 0;
#pragma unroll
        for (int k = 0; k < KPT; ++k) { sh_reg[k] = BIG; shf[k] = 3e38f; }
        for (int i = tid; i < g; i += NT) s_inSR[i] = (i == cur) ? 1 : 0;
        if (tid == 0) { s_i = cur; s_sink = -1; s_minval = 0.0; s_packed = ~0ULL; }
        __syncthreads();

        // ---- Dijkstra over columns ----
        while (true) {
            const int i = s_i;
            const double scal = s_minval - s_u[i];   // hoisted (validated R2 form)
            const float scalf = (float)scal;
            const float* __restrict__ crow = cost + i * NQ;

            // branchless fp32 screen: which of my 8 columns might improve?
            float cf_arr[KPT];
            unsigned mask = 0;
#pragma unroll
            for (int k = 0; k < KPT; ++k) {
                const int j = tid + (k << 7);
                const float cf = __ldg(crow + j);
                cf_arr[k] = cf;
                const float rf = (scalf + cf) - vf[k];
                const bool cand = (!((scmask >> k) & 1u)) && (rf < shf[k] + MARGIN);
                mask |= cand ? (1u << k) : 0u;
            }

            // ONE divergent region: exact fp64 update for screened columns only
            if (mask) {
                do {
                    const int k = __ffs(mask) - 1;
                    mask &= mask - 1;
                    const int j = tid + (k << 7);
                    double r = (scal + (double)cf_arr[k]) - v_reg[k];
                    if (r < sh_reg[k]) {
                        sh_reg[k] = r;
                        shf[k] = (float)r;
                        s_short[j] = r;
                        s_path[j] = (unsigned char)i;
                        if (r < lbest) { lbest = r; lidx = j; }
                    }
                } while (mask);
            }

            if (lbest < BIG) atomicMin(&s_packed, packkey(lbest, lidx));
            __syncthreads();

            if (tid == 0) {
                const int bidx = (int)(s_packed & 1023ULL);
                s_bidx = bidx;
                s_minval = s_short[bidx];            // exact shortest value
                s_packed = ~0ULL;
                const int rc = s_row4col[bidx];
                if (rc < 0) s_sink = bidx;
                else { s_i = rc; s_inSR[rc] = 1; }
            }
            __syncthreads();

            // owner of the newly-visited column removes it and rescans its regs
            const int bidx = s_bidx;
            if ((bidx & (NT - 1)) == tid) {
                const int kk = bidx >> 7;
                scmask |= 1u << kk;
                lbest = BIG; lidx = 0;
#pragma unroll
                for (int k = 0; k < KPT; ++k) {
                    if (!((scmask >> k) & 1u) && sh_reg[k] < lbest) {
                        lbest = sh_reg[k];
                        lidx = tid + (k << 7);
                    }
                }
            }
            if (s_sink >= 0) break;
        }

        const double mv = s_minval;
        const int sink = s_sink;

        // ---- dual updates (pre-augment col4row) ----
#pragma unroll
        for (int k = 0; k < KPT; ++k) {
            if ((scmask >> k) & 1u) {
                v_reg[k] -= (mv - sh_reg[k]);
                vf[k] = (float)v_reg[k];
            }
        }
        for (int i = tid; i < g; i += NT) {
            if (i == cur) s_u[i] += mv;
            else if (s_inSR[i]) s_u[i] += (mv - s_short[s_col4row[i]]);
        }
        __syncthreads();

        // ---- augment alternating path (serial, short) ----
        if (tid == 0) {
            int j = sink;
            while (true) {
                const int i = s_path[j];
                s_row4col[j] = (short)i;
                const short nj = s_col4row[i];
                s_col4row[i] = (short)j;
                j = nj;
                if (i == cur) break;
            }
        }
        __syncthreads();
    }

    // outputs: proposal p = col4row[i] gets index i, mask 1
    for (int i = tid; i < g; i += NT) {
        const int p = s_col4row[i];
        outi[p] = (float)i;
        outm[p] = 1.0f;
    }
}

extern "C" void kernel_launch(void* const* d_in, const int* in_sizes, int n_in,
                              void* d_out, int out_size) {
    const float* obj = (const float*)d_in[1];
    const float* cd  = (const float*)d_in[2];
    const float* gi  = (const float*)d_in[3];
    const int* ngt   = (const int*)d_in[4];
    float* out = (float*)d_out;

    const int total = NB * NG * NQ;
    build_cost_kernel<<<(total + 255) / 256, 256>>>(obj, cd, gi);
    solve_kernel<<<NB, NT>>>(ngt, out);
}